// round 1
// baseline (speedup 1.0000x reference)
#include <cuda_runtime.h>

#define ROWS      4096
#define FDIM      16384
#define BINS      128
#define NFEAT     257          // 128 counts + 129 boundaries
#define FEAT_PAD  260          // padded to multiple of 4 for float4 epilogue
#define OUT       64
#define HBLOCK    512
#define NWARPS    (HBLOCK / 32)
#define ROWS_PER_BLK 16

// Scratch (no allocs allowed in kernel_launch)
__device__ __align__(16) float g_feats[ROWS * FEAT_PAD];
__device__ __align__(16) float g_WT[FEAT_PAD * OUT];

// ---------------------------------------------------------------------------
// Kernel 1: per-row min/max + histogram + boundaries, single DRAM pass.
// One CTA per row; row data lives in registers (8 x float4 per thread).
// ---------------------------------------------------------------------------
__global__ __launch_bounds__(HBLOCK) void hist_kernel(const float* __restrict__ x) {
    const int row  = blockIdx.x;
    const int tid  = threadIdx.x;
    const int warp = tid >> 5;
    const int lane = tid & 31;

    __shared__ unsigned int hist[NWARPS * BINS];   // 8 KB, per-warp privatized
    __shared__ float s_red[2 * NWARPS];
    __shared__ float s_mnw[2];

    // zero histograms (covered by the first __syncthreads below)
    #pragma unroll
    for (int k = 0; k < (NWARPS * BINS) / HBLOCK; k++)
        hist[tid + k * HBLOCK] = 0u;

    // coalesced load of the whole row into registers
    const float4* xr = reinterpret_cast<const float4*>(x) + (size_t)row * (FDIM / 4);
    float4 v[8];
    #pragma unroll
    for (int k = 0; k < 8; k++) v[k] = xr[tid + k * HBLOCK];

    // thread-local min/max
    float mn = v[0].x, mx = v[0].x;
    #pragma unroll
    for (int k = 0; k < 8; k++) {
        mn = fminf(mn, fminf(fminf(v[k].x, v[k].y), fminf(v[k].z, v[k].w)));
        mx = fmaxf(mx, fmaxf(fmaxf(v[k].x, v[k].y), fmaxf(v[k].z, v[k].w)));
    }
    // warp reduce
    #pragma unroll
    for (int o = 16; o > 0; o >>= 1) {
        mn = fminf(mn, __shfl_xor_sync(0xffffffffu, mn, o));
        mx = fmaxf(mx, __shfl_xor_sync(0xffffffffu, mx, o));
    }
    if (lane == 0) { s_red[warp] = mn; s_red[NWARPS + warp] = mx; }
    __syncthreads();
    if (tid == 0) {
        float m = s_red[0], M = s_red[NWARPS];
        #pragma unroll
        for (int i = 1; i < NWARPS; i++) {
            m = fminf(m, s_red[i]);
            M = fmaxf(M, s_red[NWARPS + i]);
        }
        s_mnw[0] = m;
        s_mnw[1] = M - m;
    }
    __syncthreads();

    const float row_mn = s_mnw[0];
    const float width  = s_mnw[1];
    const float invw   = 128.0f / ((width == 0.0f) ? 1.0f : width);

    // histogram into this warp's private table
    unsigned int* h = &hist[warp * BINS];
    #pragma unroll
    for (int k = 0; k < 8; k++) {
        float vals[4] = {v[k].x, v[k].y, v[k].z, v[k].w};
        #pragma unroll
        for (int e = 0; e < 4; e++) {
            int b = (int)floorf((vals[e] - row_mn) * invw);
            b = min(BINS - 1, max(0, b));
            atomicAdd(&h[b], 1u);
        }
    }
    __syncthreads();

    // emit feats: counts/16384, boundaries, zero pad
    float* fr = &g_feats[(size_t)row * FEAT_PAD];
    if (tid < BINS) {
        unsigned int c = 0;
        #pragma unroll
        for (int w = 0; w < NWARPS; w++) c += hist[w * BINS + tid];
        fr[tid] = (float)c * (1.0f / 16384.0f);
    } else if (tid < NFEAT) {
        int k = tid - BINS;                       // 0..128
        float t = (float)k * (1.0f / 128.0f);     // exact (k/2^7)
        fr[tid] = row_mn + t * width;
    } else if (tid < FEAT_PAD) {
        fr[tid] = 0.0f;
    }
}

// ---------------------------------------------------------------------------
// Prep: transpose + zero-pad W[64][257] -> WT[260][64] for coalesced float4 reads
// ---------------------------------------------------------------------------
__global__ void prep_WT(const float* __restrict__ W) {
    int idx = blockIdx.x * blockDim.x + threadIdx.x;
    if (idx >= FEAT_PAD * OUT) return;
    int i = idx >> 6;    // feature index 0..259
    int j = idx & 63;    // output index
    g_WT[idx] = (i < NFEAT) ? W[j * NFEAT + i] : 0.0f;
}

// ---------------------------------------------------------------------------
// Kernel 2: out[4096][64] = feats @ W^T + b.
// 16 rows per block; each thread owns (row, 4 outputs); WT reads are
// coalesced float4 and L1-resident after warmup.
// ---------------------------------------------------------------------------
__global__ __launch_bounds__(256) void gemm_kernel(const float* __restrict__ bias,
                                                   float* __restrict__ out) {
    __shared__ float sf[ROWS_PER_BLK * FEAT_PAD];   // 16.6 KB
    const int row0 = blockIdx.x * ROWS_PER_BLK;
    const int tid  = threadIdx.x;

    const float* src = &g_feats[(size_t)row0 * FEAT_PAD];
    for (int i = tid; i < ROWS_PER_BLK * FEAT_PAD; i += 256) sf[i] = src[i];
    __syncthreads();

    const int r  = tid >> 4;   // local row 0..15
    const int j4 = tid & 15;   // output group (4 outputs each)

    const float4* WT4 = reinterpret_cast<const float4*>(g_WT);
    const float*  f   = &sf[r * FEAT_PAD];

    float4 acc = make_float4(0.f, 0.f, 0.f, 0.f);
    #pragma unroll 4
    for (int i = 0; i < FEAT_PAD; i++) {          // pad entries are 0 in both operands
        float4 w = WT4[i * (OUT / 4) + j4];
        float fv = f[i];
        acc.x += fv * w.x;
        acc.y += fv * w.y;
        acc.z += fv * w.z;
        acc.w += fv * w.w;
    }
    float4 bb = reinterpret_cast<const float4*>(bias)[j4];
    float4 o  = make_float4(acc.x + bb.x, acc.y + bb.y, acc.z + bb.z, acc.w + bb.w);
    reinterpret_cast<float4*>(out)[(row0 + r) * (OUT / 4) + j4] = o;
}

// ---------------------------------------------------------------------------
extern "C" void kernel_launch(void* const* d_in, const int* in_sizes, int n_in,
                              void* d_out, int out_size) {
    const float* x    = (const float*)d_in[0];   // [4096, 16384]
    const float* W    = (const float*)d_in[1];   // [64, 257]
    const float* bias = (const float*)d_in[2];   // [64]
    float* out = (float*)d_out;                  // [4096, 64]

    prep_WT<<<(FEAT_PAD * OUT + 255) / 256, 256>>>(W);
    hist_kernel<<<ROWS, HBLOCK>>>(x);
    gemm_kernel<<<ROWS / ROWS_PER_BLK, 256>>>(bias, out);
}

// round 3
// speedup vs baseline: 1.3488x; 1.3488x over previous
#include <cuda_runtime.h>

#define ROWS   4096
#define FDIM   16384
#define BINS   128
#define NFEAT  257            // 128 counts + 129 boundaries
#define FPAD   288            // padded: 32 parts x 9 float4-friendly, zeros beyond 257
#define OUT    64
#define HB     512
#define NW     (HB / 32)      // 16 warps

// One-time transposed+padded weights: WT[i][j], i<288, j<64 (zeros for i>=257)
__device__ __align__(16) float g_WT[FPAD * OUT];

// ---------------------------------------------------------------------------
__global__ void prep_WT(const float* __restrict__ W) {
    int idx = blockIdx.x * blockDim.x + threadIdx.x;
    if (idx >= FPAD * OUT) return;
    int i = idx >> 6;         // feature 0..287
    int j = idx & 63;         // output
    g_WT[idx] = (i < NFEAT) ? W[j * NFEAT + i] : 0.0f;
}

// ---------------------------------------------------------------------------
// Fused: per-row min/max + histogram + boundaries + (feats @ W^T + b).
// One CTA per row; row lives in registers (8 x float4 per thread).
// ---------------------------------------------------------------------------
__global__ __launch_bounds__(HB, 2) void fused_kernel(const float* __restrict__ x,
                                                      const float* __restrict__ bias,
                                                      float* __restrict__ out) {
    const int row  = blockIdx.x;
    const int tid  = threadIdx.x;
    const int warp = tid >> 5;
    const int lane = tid & 31;

    __shared__ unsigned int hist[NW * BINS];   // 8 KB, per-warp privatized
    __shared__ float  s_red[2 * NW];
    __shared__ float  s_mnw[2];
    __shared__ float  sf[FPAD];                // feats (padded with zeros)
    __shared__ float4 spart[NW * 16];          // dot partials [warp][j4]

    // zero histograms + feats pad (covered by first __syncthreads)
    #pragma unroll
    for (int k = 0; k < (NW * BINS) / HB; k++)
        hist[tid + k * HB] = 0u;
    if (tid < FPAD - NFEAT) sf[NFEAT + tid] = 0.0f;   // 31 pad zeros

    // coalesced load of the whole row into registers
    const float4* xr = reinterpret_cast<const float4*>(x) + (size_t)row * (FDIM / 4);
    float4 v[8];
    #pragma unroll
    for (int k = 0; k < 8; k++) v[k] = xr[tid + k * HB];

    // thread-local min/max
    float mn = v[0].x, mx = v[0].x;
    #pragma unroll
    for (int k = 0; k < 8; k++) {
        mn = fminf(mn, fminf(fminf(v[k].x, v[k].y), fminf(v[k].z, v[k].w)));
        mx = fmaxf(mx, fmaxf(fmaxf(v[k].x, v[k].y), fmaxf(v[k].z, v[k].w)));
    }
    #pragma unroll
    for (int o = 16; o > 0; o >>= 1) {
        mn = fminf(mn, __shfl_xor_sync(0xffffffffu, mn, o));
        mx = fmaxf(mx, __shfl_xor_sync(0xffffffffu, mx, o));
    }
    if (lane == 0) { s_red[warp] = mn; s_red[NW + warp] = mx; }
    __syncthreads();
    if (tid == 0) {
        float m = s_red[0], M = s_red[NW];
        #pragma unroll
        for (int i = 1; i < NW; i++) {
            m = fminf(m, s_red[i]);
            M = fmaxf(M, s_red[NW + i]);
        }
        s_mnw[0] = m;
        s_mnw[1] = M - m;
    }
    __syncthreads();

    const float row_mn = s_mnw[0];
    const float width  = s_mnw[1];
    const float invw   = 128.0f / ((width == 0.0f) ? 1.0f : width);
    const float nmn    = -row_mn * invw;       // fused offset

    // histogram: v >= mn guarantees the FMA result >= -1ulp, so int-trunc
    // both implements floor (for >=0) and the lower clamp (tiny negatives -> 0).
    unsigned int* h = &hist[warp * BINS];
    #pragma unroll
    for (int k = 0; k < 8; k++) {
        float vals[4] = {v[k].x, v[k].y, v[k].z, v[k].w};
        #pragma unroll
        for (int e = 0; e < 4; e++) {
            int b = (int)__fmaf_rn(vals[e], invw, nmn);
            b = min(b, BINS - 1);
            atomicAdd(&h[b], 1u);
        }
    }
    __syncthreads();

    // feats into shared: counts/16384, then boundaries
    if (tid < BINS) {
        unsigned int c = 0;
        #pragma unroll
        for (int w = 0; w < NW; w++) c += hist[w * BINS + tid];
        sf[tid] = (float)c * (1.0f / 16384.0f);
    } else if (tid < NFEAT) {
        int k = tid - BINS;                        // 0..128
        float t = (float)k * (1.0f / 128.0f);      // exact
        sf[tid] = row_mn + t * width;
    }
    __syncthreads();

    // out[row][:] = sf . WT + bias
    // thread t: j4 = 4-output group (float4 of WT row), p = i-partition (0..31)
    const int j4 = tid & 15;
    const int p  = tid >> 4;
    const float4* WT4 = reinterpret_cast<const float4*>(g_WT);

    float4 acc = make_float4(0.f, 0.f, 0.f, 0.f);
    #pragma unroll
    for (int k = 0; k < FPAD / 32; k++) {          // 9 iters
        int i = p * (FPAD / 32) + k;               // 0..287
        float  fv = sf[i];
        float4 wv = WT4[i * (OUT / 4) + j4];
        acc.x += fv * wv.x;
        acc.y += fv * wv.y;
        acc.z += fv * wv.z;
        acc.w += fv * wv.w;
    }
    // lanes l and l^16 share j4, differ in p -> fold
    acc.x += __shfl_xor_sync(0xffffffffu, acc.x, 16);
    acc.y += __shfl_xor_sync(0xffffffffu, acc.y, 16);
    acc.z += __shfl_xor_sync(0xffffffffu, acc.z, 16);
    acc.w += __shfl_xor_sync(0xffffffffu, acc.w, 16);
    if (lane < 16) spart[warp * 16 + lane] = acc;
    __syncthreads();

    if (tid < OUT) {
        const float* sp = reinterpret_cast<const float*>(spart);  // [16][64]
        float s = 0.0f;
        #pragma unroll
        for (int w = 0; w < NW; w++) s += sp[w * OUT + tid];
        out[(size_t)row * OUT + tid] = s + bias[tid];
    }
}

// ---------------------------------------------------------------------------
extern "C" void kernel_launch(void* const* d_in, const int* in_sizes, int n_in,
                              void* d_out, int out_size) {
    const float* x    = (const float*)d_in[0];   // [4096, 16384]
    const float* W    = (const float*)d_in[1];   // [64, 257]
    const float* bias = (const float*)d_in[2];   // [64]
    float* out = (float*)d_out;                  // [4096, 64]

    prep_WT<<<(FPAD * OUT + 255) / 256, 256>>>(W);
    fused_kernel<<<ROWS, HB>>>(x, bias, out);
}